// round 1
// baseline (speedup 1.0000x reference)
#include <cuda_runtime.h>
#include <cuda_bf16.h>

// Problem constants
#define BATCH 64
#define SRC   512
#define HID   1024
#define HID2  2048
#define NEGV  -1e10f

// Scratch (no cudaMalloc allowed)
__device__ float g_c[BATCH * HID];        // Wh + W_b + U_b
__device__ float g_energy[BATCH * SRC];   // pre-mask energies

// ---------------- packed f32x2 helpers ----------------
static __device__ __forceinline__ void ffma2(unsigned long long &c,
                                             unsigned long long a,
                                             unsigned long long b) {
    asm("fma.rn.f32x2 %0, %1, %2, %0;" : "+l"(c) : "l"(a), "l"(b));
}
static __device__ __forceinline__ unsigned long long splat2(float x) {
    unsigned long long r;
    asm("mov.b64 %0, {%1, %1};" : "=l"(r) : "f"(x));
    return r;
}
static __device__ __forceinline__ void unpack2(unsigned long long v, float &lo, float &hi) {
    asm("mov.b64 {%0, %1}, %2;" : "=f"(lo), "=f"(hi) : "l"(v));
}

static __device__ __forceinline__ float fast_tanh(float x) {
    x = fminf(fmaxf(x, -12.f), 12.f);
    float t = __expf(2.f * x);
    return (t - 1.f) * __frcp_rn(t + 1.f);
}

// ---------------- K1: c[b,h] = hidden[b,:] . W_w[h,:] + W_b[h] + U_b[h] ----------------
__global__ void k1_wh(const float* __restrict__ hidden,
                      const float* __restrict__ W_w,
                      const float* __restrict__ W_b,
                      const float* __restrict__ U_b) {
    int b = blockIdx.x;
    __shared__ __align__(16) float hs[HID];
    int t = threadIdx.x;               // 256 threads
    ((float4*)hs)[t] = ((const float4*)(hidden + (size_t)b * HID))[t];
    __syncthreads();
    int warp = t >> 5, lane = t & 31;
    for (int h = warp; h < HID; h += 8) {
        const float4* wr = (const float4*)(W_w + (size_t)h * HID);
        const float4* hr = (const float4*)hs;
        float s0 = 0.f, s1 = 0.f, s2 = 0.f, s3 = 0.f;
        #pragma unroll
        for (int i = 0; i < 8; i++) {
            int idx = lane + i * 32;   // float4 index 0..255
            float4 w = wr[idx];
            float4 hv = hr[idx];
            s0 += w.x * hv.x; s1 += w.y * hv.y;
            s2 += w.z * hv.z; s3 += w.w * hv.w;
        }
        float s = (s0 + s1) + (s2 + s3);
        #pragma unroll
        for (int off = 16; off; off >>= 1) s += __shfl_xor_sync(0xffffffffu, s, off);
        if (lane == 0) g_c[b * HID + h] = s + W_b[h] + U_b[h];
    }
}

// ---------------- K2: fused energy GEMM + tanh/v reduction ----------------
// grid (4 stiles, 64 batches), 128 threads. Tile: M=128 (s), N=64 (h per pass), KT=16.
// Microtile 8x8 per thread via fma.rn.f32x2.
__global__ __launch_bounds__(128) void k2_energy(const float* __restrict__ enc,
                                                 const float* __restrict__ U_w,
                                                 const float* __restrict__ v_w) {
    const int b  = blockIdx.y;
    const int st = blockIdx.x;
    const int s0 = st * 128;
    const int t  = threadIdx.x;

    __shared__ __align__(16) float As[2][16][132];   // [buf][kk][m]
    __shared__ __align__(16) float Bs[2][16][72];    // [buf][kk][n]
    __shared__ float red[128];

    // A loader: thread t owns s-row m = t; loads 16 k's per tile as 4 float4.
    const float* encRow = enc + ((size_t)((s0 + t) * BATCH + b)) * HID2;
    // B loader: n = t&63, half = t>>6 loads 8 consecutive k's (2 float4).
    const int nB   = t & 63;
    const int half = t >> 6;

    const int tx = t & 15, ty = t >> 4;
    const int m0 = tx * 8, n0l = ty * 8;

    float esum[8];
    #pragma unroll
    for (int i = 0; i < 8; i++) esum[i] = 0.f;

    for (int nt = 0; nt < 16; nt++) {
        const int n0 = nt * 64;
        const float* uBase = U_w + (size_t)(n0 + nB) * HID2 + half * 8;

        unsigned long long cc[8][4];
        #pragma unroll
        for (int i = 0; i < 8; i++)
            #pragma unroll
            for (int j = 0; j < 4; j++) cc[i][j] = 0ULL;

        // prologue: tile kt=0 -> buf 0
        {
            #pragma unroll
            for (int i = 0; i < 4; i++) {
                float4 v = *(const float4*)(encRow + i * 4);
                As[0][4 * i + 0][t] = v.x; As[0][4 * i + 1][t] = v.y;
                As[0][4 * i + 2][t] = v.z; As[0][4 * i + 3][t] = v.w;
            }
            #pragma unroll
            for (int j = 0; j < 2; j++) {
                float4 v = *(const float4*)(uBase + j * 4);
                int kb = half * 8 + j * 4;
                Bs[0][kb + 0][nB] = v.x; Bs[0][kb + 1][nB] = v.y;
                Bs[0][kb + 2][nB] = v.z; Bs[0][kb + 3][nB] = v.w;
            }
        }
        __syncthreads();

        for (int kt = 0; kt < 128; kt++) {
            const int cur = kt & 1;
            float4 pa[4], pb[2];
            if (kt < 127) {
                const int k0 = (kt + 1) * 16;
                #pragma unroll
                for (int i = 0; i < 4; i++) pa[i] = *(const float4*)(encRow + k0 + i * 4);
                #pragma unroll
                for (int j = 0; j < 2; j++) pb[j] = *(const float4*)(uBase + k0 + j * 4);
            }
            // compute current buffer
            #pragma unroll
            for (int kk = 0; kk < 16; kk++) {
                float4 a0 = *(const float4*)&As[cur][kk][m0];
                float4 a1 = *(const float4*)&As[cur][kk][m0 + 4];
                unsigned long long aa[8];
                aa[0] = splat2(a0.x); aa[1] = splat2(a0.y);
                aa[2] = splat2(a0.z); aa[3] = splat2(a0.w);
                aa[4] = splat2(a1.x); aa[5] = splat2(a1.y);
                aa[6] = splat2(a1.z); aa[7] = splat2(a1.w);
                ulonglong2 bq0 = *(const ulonglong2*)&Bs[cur][kk][n0l];
                ulonglong2 bq1 = *(const ulonglong2*)&Bs[cur][kk][n0l + 4];
                unsigned long long bb[4] = {bq0.x, bq0.y, bq1.x, bq1.y};
                #pragma unroll
                for (int i = 0; i < 8; i++)
                    #pragma unroll
                    for (int j = 0; j < 4; j++) ffma2(cc[i][j], aa[i], bb[j]);
            }
            if (kt < 127) {
                const int nxt = cur ^ 1;
                #pragma unroll
                for (int i = 0; i < 4; i++) {
                    As[nxt][4 * i + 0][t] = pa[i].x; As[nxt][4 * i + 1][t] = pa[i].y;
                    As[nxt][4 * i + 2][t] = pa[i].z; As[nxt][4 * i + 3][t] = pa[i].w;
                }
                #pragma unroll
                for (int j = 0; j < 2; j++) {
                    int kb = half * 8 + j * 4;
                    Bs[nxt][kb + 0][nB] = pb[j].x; Bs[nxt][kb + 1][nB] = pb[j].y;
                    Bs[nxt][kb + 2][nB] = pb[j].z; Bs[nxt][kb + 3][nB] = pb[j].w;
                }
            }
            __syncthreads();
        }

        // epilogue: tanh + v reduction for this n-tile
        float cadd[8], vv[8];
        #pragma unroll
        for (int j = 0; j < 8; j++) {
            int h = n0 + n0l + j;
            cadd[j] = g_c[b * HID + h];
            vv[j]   = v_w[h];
        }
        #pragma unroll
        for (int i = 0; i < 8; i++) {
            #pragma unroll
            for (int j = 0; j < 4; j++) {
                float lo, hi;
                unpack2(cc[i][j], lo, hi);
                float e0 = fast_tanh(cadd[2 * j] + lo);
                float e1 = fast_tanh(cadd[2 * j + 1] + hi);
                esum[i] += vv[2 * j] * e0 + vv[2 * j + 1] * e1;
            }
        }
    }

    // cross-ty reduction of esum into per-row energy
    red[t] = 0.f;
    __syncthreads();
    #pragma unroll
    for (int i = 0; i < 8; i++) atomicAdd(&red[m0 + i], esum[i]);
    __syncthreads();
    g_energy[b * SRC + s0 + t] = red[t];
}

// ---------------- K3: masked softmax over S per batch ----------------
__global__ void k3_softmax(const void* __restrict__ mask_raw,
                           float* __restrict__ out) {
    const int b = blockIdx.x;
    const int t = threadIdx.x;      // 512 threads
    const int lane = t & 31, wid = t >> 5;

    __shared__ int s_mode;          // 0 = int32 mask, 1 = byte mask
    __shared__ float sm[16];
    __shared__ float s_bcast;

    if (t == 0) s_mode = 0;
    __syncthreads();
    if (t < 256) {
        unsigned w = ((const unsigned*)mask_raw)[t];
        if (w > 1u) atomicOr(&s_mode, 1);
    }
    __syncthreads();

    int masked;
    if (s_mode)
        masked = ((const unsigned char*)mask_raw)[b * SRC + t];
    else
        masked = ((const int*)mask_raw)[b * SRC + t];

    float e = masked ? NEGV : g_energy[b * SRC + t];

    // block max
    float m = e;
    #pragma unroll
    for (int off = 16; off; off >>= 1) m = fmaxf(m, __shfl_xor_sync(0xffffffffu, m, off));
    if (lane == 0) sm[wid] = m;
    __syncthreads();
    if (wid == 0) {
        float v = (lane < 16) ? sm[lane] : -3.4e38f;
        #pragma unroll
        for (int off = 8; off; off >>= 1) v = fmaxf(v, __shfl_xor_sync(0xffffffffu, v, off));
        if (lane == 0) s_bcast = v;
    }
    __syncthreads();
    float mx = s_bcast;

    float p = __expf(e - mx);

    // block sum
    float s = p;
    #pragma unroll
    for (int off = 16; off; off >>= 1) s += __shfl_xor_sync(0xffffffffu, s, off);
    __syncthreads();
    if (lane == 0) sm[wid] = s;
    __syncthreads();
    if (wid == 0) {
        float v = (lane < 16) ? sm[lane] : 0.f;
        #pragma unroll
        for (int off = 8; off; off >>= 1) v += __shfl_xor_sync(0xffffffffu, v, off);
        if (lane == 0) s_bcast = v;
    }
    __syncthreads();
    float tot = s_bcast;

    out[b * SRC + t] = p * __frcp_rn(tot);
}

// ---------------- launch ----------------
extern "C" void kernel_launch(void* const* d_in, const int* in_sizes, int n_in,
                              void* d_out, int out_size) {
    const float* hidden = (const float*)d_in[0];
    const float* enc    = (const float*)d_in[1];
    const void*  mask   = d_in[2];
    const float* W_w    = (const float*)d_in[3];
    const float* W_b    = (const float*)d_in[4];
    const float* U_w    = (const float*)d_in[5];
    const float* U_b    = (const float*)d_in[6];
    const float* v_w    = (const float*)d_in[7];
    float* out = (float*)d_out;

    k1_wh<<<BATCH, 256>>>(hidden, W_w, W_b, U_b);
    dim3 g2(4, BATCH);
    k2_energy<<<g2, 128>>>(enc, U_w, v_w);
    k3_softmax<<<BATCH, 512>>>(mask, out);
}

// round 3
// speedup vs baseline: 3.3929x; 3.3929x over previous
#include <cuda_runtime.h>
#include <cuda_bf16.h>
#include <cstdint>

#define BATCH 64
#define SRC   512
#define HID   1024
#define HID2  2048
#define NEGV  -1e10f

// ------------------------------------------------------------------
// scratch (static device globals; no cudaMalloc allowed)
// ------------------------------------------------------------------
__device__ __align__(16) __nv_bfloat16 g_encH[SRC * BATCH * HID2];
__device__ __align__(16) __nv_bfloat16 g_encL[SRC * BATCH * HID2];
__device__ __align__(16) __nv_bfloat16 g_UH[HID * HID2];
__device__ __align__(16) __nv_bfloat16 g_UL[HID * HID2];
__device__ float g_c[BATCH * HID];
__device__ float g_energy[BATCH * SRC];

// ------------------------------------------------------------------
static __device__ __forceinline__ uint32_t smem_u32(const void* p) {
    uint32_t a;
    asm("{ .reg .u64 t; cvta.to.shared.u64 t, %1; cvt.u32.u64 %0, t; }" : "=r"(a) : "l"(p));
    return a;
}
static __device__ __forceinline__ void cp16(uint32_t dst, const void* src) {
    asm volatile("cp.async.cg.shared.global [%0], [%1], 16;" :: "r"(dst), "l"(src));
}
#define CP_COMMIT() asm volatile("cp.async.commit_group;" ::: "memory")
#define CP_WAIT(n)  asm volatile("cp.async.wait_group %0;" :: "n"(n) : "memory")

static __device__ __forceinline__ void ldm_x4(uint32_t* r, uint32_t addr) {
    asm volatile("ldmatrix.sync.aligned.m8n8.x4.shared.b16 {%0,%1,%2,%3}, [%4];"
                 : "=r"(r[0]), "=r"(r[1]), "=r"(r[2]), "=r"(r[3]) : "r"(addr));
}
static __device__ __forceinline__ void mma_bf16(float* c, const uint32_t* a,
                                                uint32_t b0, uint32_t b1) {
    asm volatile(
        "mma.sync.aligned.m16n8k16.row.col.f32.bf16.bf16.f32 "
        "{%0,%1,%2,%3}, {%4,%5,%6,%7}, {%8,%9}, {%0,%1,%2,%3};"
        : "+f"(c[0]), "+f"(c[1]), "+f"(c[2]), "+f"(c[3])
        : "r"(a[0]), "r"(a[1]), "r"(a[2]), "r"(a[3]), "r"(b0), "r"(b1));
}

// SMEM layout (bytes). Tile rows: 32 bf16 (64B) + 16B pad = 80B stride.
#define RSTRIDE   80
#define TILE_BYTES (128 * RSTRIDE)        // 10240 per (buf,split)
#define OFF_A     0                        // 4 tiles: (buf*2+split)
#define OFF_B     40960
#define OFF_CS    81920
#define OFF_VS    86016
#define OFF_RED   90112
#define SMEM_TOTAL 90624

// ------------------------------------------------------------------
// prep: fp32 -> bf16 hi/lo splits
// ------------------------------------------------------------------
static __device__ __forceinline__ void split4(float4 v, __nv_bfloat16* H, __nv_bfloat16* L) {
    float a[4] = {v.x, v.y, v.z, v.w};
    #pragma unroll
    for (int j = 0; j < 4; j++) {
        __nv_bfloat16 h = __float2bfloat16_rn(a[j]);
        H[j] = h;
        L[j] = __float2bfloat16_rn(a[j] - __bfloat162float(h));
    }
}
__global__ void conv_enc(const float* __restrict__ enc) {
    size_t i = (size_t)blockIdx.x * 256 + threadIdx.x;
    float4 v = ((const float4*)enc)[i];
    __nv_bfloat16 h[4], l[4];
    split4(v, h, l);
    *(uint2*)(g_encH + 4 * i) = *(uint2*)h;
    *(uint2*)(g_encL + 4 * i) = *(uint2*)l;
}
__global__ void conv_U(const float* __restrict__ U_w) {
    size_t i = (size_t)blockIdx.x * 256 + threadIdx.x;
    float4 v = ((const float4*)U_w)[i];
    __nv_bfloat16 h[4], l[4];
    split4(v, h, l);
    *(uint2*)(g_UH + 4 * i) = *(uint2*)h;
    *(uint2*)(g_UL + 4 * i) = *(uint2*)l;
}

// ------------------------------------------------------------------
// K1: g_c[b,h] = hidden[b,:] . W_w[h,:] + W_b[h] + U_b[h]
// ------------------------------------------------------------------
__global__ void k1_wh(const float* __restrict__ hidden,
                      const float* __restrict__ W_w,
                      const float* __restrict__ W_b,
                      const float* __restrict__ U_b) {
    int b = blockIdx.y, h0 = blockIdx.x * 128;
    __shared__ __align__(16) float hs[HID];
    int t = threadIdx.x;                    // 256
    ((float4*)hs)[t] = ((const float4*)(hidden + (size_t)b * HID))[t];
    __syncthreads();
    int w = t >> 5, lane = t & 31;
    #pragma unroll 4
    for (int hh = 0; hh < 16; hh++) {
        int h = h0 + w * 16 + hh;
        const float4* wr = (const float4*)(W_w + (size_t)h * HID);
        const float4* hr = (const float4*)hs;
        float s0 = 0.f, s1 = 0.f, s2 = 0.f, s3 = 0.f;
        #pragma unroll
        for (int i = 0; i < 8; i++) {
            float4 wv = wr[lane + i * 32];
            float4 hv = hr[lane + i * 32];
            s0 += wv.x * hv.x; s1 += wv.y * hv.y;
            s2 += wv.z * hv.z; s3 += wv.w * hv.w;
        }
        float s = (s0 + s1) + (s2 + s3);
        #pragma unroll
        for (int off = 16; off; off >>= 1) s += __shfl_xor_sync(0xffffffffu, s, off);
        if (lane == 0) g_c[b * HID + h] = s + W_b[h] + U_b[h];
    }
}

// ------------------------------------------------------------------
// K2: tensor-core (mma.sync bf16, 3-term split) fused energy
//   energy[b,s] = sum_h v[h] * tanh(c[b,h] + sum_k enc[s,b,k]*U[h,k])
// CTA: 256 thr, tile M=128 (s) x N=128 (h per chunk, 8 chunks), K-chunk 32.
// Warps: wm = wid&3 (rows wm*32..+31), wn = wid>>2 (cols wn*64..+63).
// ------------------------------------------------------------------
__global__ __launch_bounds__(256, 2) void k2_energy(const float* __restrict__ v_w) {
    extern __shared__ __align__(128) char smem[];
    const uint32_t sb = smem_u32(smem);
    const int b = blockIdx.y, s0 = blockIdx.x * 128;
    const int t = threadIdx.x, wid = t >> 5, lane = t & 31;
    const int wm = wid & 3, wn = wid >> 2;

    float* cs = (float*)(smem + OFF_CS);
    float* vs = (float*)(smem + OFF_VS);
    for (int i = t; i < HID; i += 256) { cs[i] = g_c[b * HID + i]; vs[i] = v_w[i]; }

    const size_t ARS = (size_t)BATCH * HID2;     // enc row stride (elems)
    const __nv_bfloat16* encHb = g_encH + ((size_t)s0 * BATCH + b) * HID2;
    const __nv_bfloat16* encLb = g_encL + ((size_t)s0 * BATCH + b) * HID2;

    // staging task decomposition: 4 tasks/thread for A, 4 for B
    int stg_split = t >> 7;            // 0..1 (with i*256: idx>>9)
    // per-thread ldmatrix smem offsets (within a (buf,split) tile)
    const uint32_t a_off = (uint32_t)((wm * 32 + (lane & 15)) * RSTRIDE + (lane >> 4) * 16);
    const uint32_t b_off = (uint32_t)((wn * 64 + (lane & 7) + ((lane >> 4) << 3)) * RSTRIDE
                                      + ((lane >> 3) & 1) * 16);

    float esum[4] = {0.f, 0.f, 0.f, 0.f};
    (void)stg_split;

    __syncthreads();

    for (int nc = 0; nc < 8; nc++) {
        const int n0 = nc * 128;
        float c[2][8][4];
        #pragma unroll
        for (int mt = 0; mt < 2; mt++)
            #pragma unroll
            for (int nt = 0; nt < 8; nt++)
                #pragma unroll
                for (int e = 0; e < 4; e++) c[mt][nt][e] = 0.f;

        // ---- staging helper (inlined twice) ----
        #define STAGE(CHUNK, BUF) do {                                             \
            const int _k0 = (CHUNK) * 32;                                          \
            _Pragma("unroll")                                                      \
            for (int _i = 0; _i < 4; _i++) {                                       \
                int _idx = t + _i * 256;          /* 0..1023 */                    \
                int _sp  = _idx >> 9;             /* split */                      \
                int _r   = (_idx >> 2) & 127;     /* row   */                      \
                int _kb  = _idx & 3;                                               \
                uint32_t _so = (uint32_t)(_r * RSTRIDE + _kb * 16);                \
                uint32_t _tb = (uint32_t)(((BUF) * 2 + _sp) * TILE_BYTES);         \
                const __nv_bfloat16* _ea = _sp ? encLb : encHb;                    \
                cp16(sb + OFF_A + _tb + _so, _ea + (size_t)_r * ARS + _k0 + _kb * 8); \
                const __nv_bfloat16* _ub = _sp ? g_UL : g_UH;                      \
                cp16(sb + OFF_B + _tb + _so,                                       \
                     _ub + (size_t)(n0 + _r) * HID2 + _k0 + _kb * 8);              \
            }                                                                      \
        } while (0)

        STAGE(0, 0);
        CP_COMMIT();

        for (int kt = 0; kt < 64; kt++) {
            const int buf = kt & 1;
            if (kt < 63) { STAGE(kt + 1, buf ^ 1); CP_COMMIT(); CP_WAIT(1); }
            else         { CP_WAIT(0); }
            __syncthreads();

            const uint32_t aH = sb + OFF_A + (uint32_t)(buf * 2) * TILE_BYTES + a_off;
            const uint32_t aL = aH + TILE_BYTES;
            const uint32_t bH = sb + OFF_B + (uint32_t)(buf * 2) * TILE_BYTES + b_off;
            const uint32_t bL = bH + TILE_BYTES;

            #pragma unroll
            for (int ks = 0; ks < 2; ks++) {
                const uint32_t ko = (uint32_t)(ks * 32);
                uint32_t ah[2][4], al[2][4], bb[4][4];
                #pragma unroll
                for (int mt = 0; mt < 2; mt++) ldm_x4(ah[mt], aH + ko + mt * (16 * RSTRIDE));
                #pragma unroll
                for (int g = 0; g < 4; g++)    ldm_x4(bb[g], bH + ko + g * (16 * RSTRIDE));
                // HH
                #pragma unroll
                for (int mt = 0; mt < 2; mt++)
                    #pragma unroll
                    for (int g = 0; g < 4; g++) {
                        mma_bf16(c[mt][2 * g],     ah[mt], bb[g][0], bb[g][1]);
                        mma_bf16(c[mt][2 * g + 1], ah[mt], bb[g][2], bb[g][3]);
                    }
                // LH
                #pragma unroll
                for (int mt = 0; mt < 2; mt++) ldm_x4(al[mt], aL + ko + mt * (16 * RSTRIDE));
                #pragma unroll
                for (int mt = 0; mt < 2; mt++)
                    #pragma unroll
                    for (int g = 0; g < 4; g++) {
                        mma_bf16(c[mt][2 * g],     al[mt], bb[g][0], bb[g][1]);
                        mma_bf16(c[mt][2 * g + 1], al[mt], bb[g][2], bb[g][3]);
                    }
                // HL (B-lo overwrites bb)
                #pragma unroll
                for (int g = 0; g < 4; g++)    ldm_x4(bb[g], bL + ko + g * (16 * RSTRIDE));
                #pragma unroll
                for (int mt = 0; mt < 2; mt++)
                    #pragma unroll
                    for (int g = 0; g < 4; g++) {
                        mma_bf16(c[mt][2 * g],     ah[mt], bb[g][0], bb[g][1]);
                        mma_bf16(c[mt][2 * g + 1], ah[mt], bb[g][2], bb[g][3]);
                    }
            }
            __syncthreads();
        }
        #undef STAGE

        // ---- epilogue for this 128-col chunk: tanh + v-dot ----
        #pragma unroll
        for (int mt = 0; mt < 2; mt++) {
            #pragma unroll
            for (int nt = 0; nt < 8; nt++) {
                const int h = n0 + wn * 64 + nt * 8 + 2 * (lane & 3);
                float ca0 = cs[h], ca1 = cs[h + 1];
                float v0 = vs[h], v1 = vs[h + 1];
                float x0 = ca0 + c[mt][nt][0];
                float x1 = ca1 + c[mt][nt][1];
                float x2 = ca0 + c[mt][nt][2];
                float x3 = ca1 + c[mt][nt][3];
                float t0, t1, t2, t3;
                asm("tanh.approx.f32 %0, %1;" : "=f"(t0) : "f"(x0));
                asm("tanh.approx.f32 %0, %1;" : "=f"(t1) : "f"(x1));
                asm("tanh.approx.f32 %0, %1;" : "=f"(t2) : "f"(x2));
                asm("tanh.approx.f32 %0, %1;" : "=f"(t3) : "f"(x3));
                esum[mt * 2 + 0] = fmaf(v0, t0, fmaf(v1, t1, esum[mt * 2 + 0]));
                esum[mt * 2 + 1] = fmaf(v0, t2, fmaf(v1, t3, esum[mt * 2 + 1]));
            }
        }
    }

    // ---- final row reduction ----
    #pragma unroll
    for (int i = 0; i < 4; i++) {
        esum[i] += __shfl_xor_sync(0xffffffffu, esum[i], 1);
        esum[i] += __shfl_xor_sync(0xffffffffu, esum[i], 2);
    }
    float* red = (float*)(smem + OFF_RED);
    __syncthreads();
    if (t < 128) red[t] = 0.f;
    __syncthreads();
    if ((lane & 3) == 0) {
        #pragma unroll
        for (int i = 0; i < 4; i++) {
            int row = wm * 32 + (i >> 1) * 16 + (lane >> 2) + (i & 1) * 8;
            atomicAdd(&red[row], esum[i]);
        }
    }
    __syncthreads();
    if (t < 128) g_energy[b * SRC + s0 + t] = red[t];
}

// ------------------------------------------------------------------
// K3: masked softmax over S per batch
// ------------------------------------------------------------------
__global__ void k3_softmax(const void* __restrict__ mask_raw, float* __restrict__ out) {
    const int b = blockIdx.x, t = threadIdx.x;
    const int lane = t & 31, wid = t >> 5;
    __shared__ int s_mode;
    __shared__ float sm[16];
    __shared__ float s_bcast;
    if (t == 0) s_mode = 0;
    __syncthreads();
    if (t < 256) {
        unsigned w = ((const unsigned*)mask_raw)[t];
        if (w > 1u) atomicOr(&s_mode, 1);
    }
    __syncthreads();
    int masked = s_mode ? (int)((const unsigned char*)mask_raw)[b * SRC + t]
                        : ((const int*)mask_raw)[b * SRC + t];
    float e = masked ? NEGV : g_energy[b * SRC + t];

    float m = e;
    #pragma unroll
    for (int off = 16; off; off >>= 1) m = fmaxf(m, __shfl_xor_sync(0xffffffffu, m, off));
    if (lane == 0) sm[wid] = m;
    __syncthreads();
    if (wid == 0) {
        float v = (lane < 16) ? sm[lane] : -3.4e38f;
        #pragma unroll
        for (int off = 8; off; off >>= 1) v = fmaxf(v, __shfl_xor_sync(0xffffffffu, v, off));
        if (lane == 0) s_bcast = v;
    }
    __syncthreads();
    float p = __expf(e - s_bcast);
    float s = p;
    #pragma unroll
    for (int off = 16; off; off >>= 1) s += __shfl_xor_sync(0xffffffffu, s, off);
    __syncthreads();
    if (lane == 0) sm[wid] = s;
    __syncthreads();
    if (wid == 0) {
        float v = (lane < 16) ? sm[lane] : 0.f;
        #pragma unroll
        for (int off = 8; off; off >>= 1) v += __shfl_xor_sync(0xffffffffu, v, off);
        if (lane == 0) s_bcast = v;
    }
    __syncthreads();
    out[b * SRC + t] = p * __frcp_rn(s_bcast);
}

// ------------------------------------------------------------------
extern "C" void kernel_launch(void* const* d_in, const int* in_sizes, int n_in,
                              void* d_out, int out_size) {
    const float* hidden = (const float*)d_in[0];
    const float* enc    = (const float*)d_in[1];
    const void*  mask   = d_in[2];
    const float* W_w    = (const float*)d_in[3];
    const float* W_b    = (const float*)d_in[4];
    const float* U_w    = (const float*)d_in[5];
    const float* U_b    = (const float*)d_in[6];
    const float* v_w    = (const float*)d_in[7];
    float* out = (float*)d_out;

    static int attr_done = 0;
    if (!attr_done) {
        cudaFuncSetAttribute(k2_energy, cudaFuncAttributeMaxDynamicSharedMemorySize, SMEM_TOTAL);
        attr_done = 1;
    }

    conv_enc<<<65536, 256>>>(enc);
    conv_U<<<2048, 256>>>(U_w);
    k1_wh<<<dim3(8, 64), 256>>>(hidden, W_w, W_b, U_b);
    k2_energy<<<dim3(4, 64), 256, SMEM_TOTAL>>>(v_w);
    k3_softmax<<<BATCH, 512>>>(mask, out);
}

// round 4
// speedup vs baseline: 4.7835x; 1.4098x over previous
#include <cuda_runtime.h>
#include <cuda_fp16.h>
#include <cstdint>

#define BATCH 64
#define SRC   512
#define HID   1024
#define HID2  2048
#define NEGV  -1e10f
#define ARS   (BATCH * HID2)

// ------------------------------------------------------------------
// scratch (static device globals; no cudaMalloc allowed)
// ------------------------------------------------------------------
__device__ __align__(16) __half g_encH[SRC * BATCH * HID2];
__device__ __align__(16) __half g_encL[SRC * BATCH * HID2];
__device__ __align__(16) __half g_UH[HID * HID2];
__device__ float g_c[BATCH * HID];
__device__ float g_energy[BATCH * SRC];

// ------------------------------------------------------------------
static __device__ __forceinline__ uint32_t smem_u32(const void* p) {
    uint32_t a;
    asm("{ .reg .u64 t; cvta.to.shared.u64 t, %1; cvt.u32.u64 %0, t; }" : "=r"(a) : "l"(p));
    return a;
}
static __device__ __forceinline__ void cp16(uint32_t dst, const void* src) {
    asm volatile("cp.async.cg.shared.global [%0], [%1], 16;" :: "r"(dst), "l"(src));
}
#define CP_COMMIT() asm volatile("cp.async.commit_group;" ::: "memory")
#define CP_WAIT(n)  asm volatile("cp.async.wait_group %0;" :: "n"(n) : "memory")

static __device__ __forceinline__ void ldm_x4(uint32_t* r, uint32_t addr) {
    asm volatile("ldmatrix.sync.aligned.m8n8.x4.shared.b16 {%0,%1,%2,%3}, [%4];"
                 : "=r"(r[0]), "=r"(r[1]), "=r"(r[2]), "=r"(r[3]) : "r"(addr));
}
static __device__ __forceinline__ void mma_f16(float* c, const uint32_t* a,
                                               uint32_t b0, uint32_t b1) {
    asm volatile(
        "mma.sync.aligned.m16n8k16.row.col.f32.f16.f16.f32 "
        "{%0,%1,%2,%3}, {%4,%5,%6,%7}, {%8,%9}, {%0,%1,%2,%3};"
        : "+f"(c[0]), "+f"(c[1]), "+f"(c[2]), "+f"(c[3])
        : "r"(a[0]), "r"(a[1]), "r"(a[2]), "r"(a[3]), "r"(b0), "r"(b1));
}

// SMEM layout. Tile rows: 32 fp16 (64B) + 16B pad = 80B stride.
#define RSTRIDE     80
#define TILE_BYTES  (128 * RSTRIDE)      // 10240
#define OFF_AH      0
#define OFF_AL      10240
#define OFF_BH      20480
#define STAGE_BYTES 30720                // per ring stage
#define OFF_CS      92160                // after 3 stages
#define OFF_VS      96256
#define OFF_RED     100352
#define SMEM_TOTAL  100864

// ------------------------------------------------------------------
// prep: fp32 -> fp16 (enc: hi+lo split; U: hi only)
// ------------------------------------------------------------------
__global__ void conv_enc(const float* __restrict__ enc) {
    size_t i = (size_t)blockIdx.x * 256 + threadIdx.x;
    float4 v = ((const float4*)enc)[i];
    float a[4] = {v.x, v.y, v.z, v.w};
    __half h[4], l[4];
    #pragma unroll
    for (int j = 0; j < 4; j++) {
        h[j] = __float2half_rn(a[j]);
        l[j] = __float2half_rn(a[j] - __half2float(h[j]));
    }
    *(uint2*)(g_encH + 4 * i) = *(uint2*)h;
    *(uint2*)(g_encL + 4 * i) = *(uint2*)l;
}
__global__ void conv_U(const float* __restrict__ U_w) {
    size_t i = (size_t)blockIdx.x * 256 + threadIdx.x;
    float4 v = ((const float4*)U_w)[i];
    float a[4] = {v.x, v.y, v.z, v.w};
    __half h[4];
    #pragma unroll
    for (int j = 0; j < 4; j++) h[j] = __float2half_rn(a[j]);
    *(uint2*)(g_UH + 4 * i) = *(uint2*)h;
}

// ------------------------------------------------------------------
// K1: g_c[b,h] = hidden[b,:] . W_w[h,:] + W_b[h] + U_b[h]
// ------------------------------------------------------------------
__global__ void k1_wh(const float* __restrict__ hidden,
                      const float* __restrict__ W_w,
                      const float* __restrict__ W_b,
                      const float* __restrict__ U_b) {
    int b = blockIdx.y, h0 = blockIdx.x * 128;
    __shared__ __align__(16) float hs[HID];
    int t = threadIdx.x;                    // 256
    ((float4*)hs)[t] = ((const float4*)(hidden + (size_t)b * HID))[t];
    __syncthreads();
    int w = t >> 5, lane = t & 31;
    #pragma unroll 4
    for (int hh = 0; hh < 16; hh++) {
        int h = h0 + w * 16 + hh;
        const float4* wr = (const float4*)(W_w + (size_t)h * HID);
        const float4* hr = (const float4*)hs;
        float s0 = 0.f, s1 = 0.f, s2 = 0.f, s3 = 0.f;
        #pragma unroll
        for (int i = 0; i < 8; i++) {
            float4 wv = wr[lane + i * 32];
            float4 hv = hr[lane + i * 32];
            s0 += wv.x * hv.x; s1 += wv.y * hv.y;
            s2 += wv.z * hv.z; s3 += wv.w * hv.w;
        }
        float s = (s0 + s1) + (s2 + s3);
        #pragma unroll
        for (int off = 16; off; off >>= 1) s += __shfl_xor_sync(0xffffffffu, s, off);
        if (lane == 0) g_c[b * HID + h] = s + W_b[h] + U_b[h];
    }
}

// ------------------------------------------------------------------
// K2: fp16 2-term mma.sync fused energy
//   energy[b,s] = sum_h v[h] * tanh(c[b,h] + sum_k enc[s,b,k]*U[h,k])
// CTA 256 thr, M=128 x N=128 per chunk (8 chunks), K-chunk 32,
// 3-stage cp.async ring, 1 barrier per k-step.
// ------------------------------------------------------------------
static __device__ __forceinline__ void do_stage(uint32_t sb, int gg, int t,
                                                const __half* __restrict__ encHb,
                                                const __half* __restrict__ encLb) {
    const int nc = gg >> 6, kt = gg & 63;
    const int k0 = kt * 32, n0 = nc * 128;
    const uint32_t sbase = sb + ((uint32_t)gg % 3u) * STAGE_BYTES;
    #pragma unroll
    for (int i = 0; i < 2; i++) {
        int idx = t + i * 256;                 // 0..511
        int r = idx >> 2, kb = idx & 3;
        uint32_t so = (uint32_t)(r * RSTRIDE + kb * 16);
        size_t goA = (size_t)r * ARS + k0 + kb * 8;
        cp16(sbase + OFF_AH + so, encHb + goA);
        cp16(sbase + OFF_AL + so, encLb + goA);
        cp16(sbase + OFF_BH + so, g_UH + (size_t)(n0 + r) * HID2 + k0 + kb * 8);
    }
}

__global__ __launch_bounds__(256, 2) void k2_energy(const float* __restrict__ v_w) {
    extern __shared__ __align__(128) char smem[];
    const uint32_t sb = smem_u32(smem);
    const int b = blockIdx.y, s0 = blockIdx.x * 128;
    const int t = threadIdx.x, wid = t >> 5, lane = t & 31;
    const int wm = wid & 3, wn = wid >> 2;

    float* cs = (float*)(smem + OFF_CS);
    float* vs = (float*)(smem + OFF_VS);
    for (int i = t; i < HID; i += 256) { cs[i] = g_c[b * HID + i]; vs[i] = v_w[i]; }

    const __half* encHb = g_encH + ((size_t)s0 * BATCH + b) * HID2;
    const __half* encLb = g_encL + ((size_t)s0 * BATCH + b) * HID2;

    // per-thread ldmatrix offsets (within a stage)
    const uint32_t a_off = (uint32_t)((wm * 32 + (lane & 15)) * RSTRIDE + (lane >> 4) * 16);
    const uint32_t b_off = (uint32_t)((wn * 64 + (lane & 7) + ((lane >> 4) << 3)) * RSTRIDE
                                      + ((lane >> 3) & 1) * 16);

    float c[2][8][4];
    #pragma unroll
    for (int mt = 0; mt < 2; mt++)
        #pragma unroll
        for (int nt = 0; nt < 8; nt++)
            #pragma unroll
            for (int e = 0; e < 4; e++) c[mt][nt][e] = 0.f;
    float esum[4] = {0.f, 0.f, 0.f, 0.f};

    do_stage(sb, 0, t, encHb, encLb);
    CP_COMMIT();
    do_stage(sb, 1, t, encHb, encLb);
    CP_COMMIT();

    for (int g = 0; g < 512; g++) {
        CP_WAIT(1);
        __syncthreads();
        if (g < 510) do_stage(sb, g + 2, t, encHb, encLb);
        CP_COMMIT();

        const uint32_t sbase = sb + ((uint32_t)g % 3u) * STAGE_BYTES;
        const uint32_t aH = sbase + OFF_AH + a_off;
        const uint32_t aL = sbase + OFF_AL + a_off;
        const uint32_t bH = sbase + OFF_BH + b_off;

        #pragma unroll
        for (int ks = 0; ks < 2; ks++) {
            const uint32_t ko = (uint32_t)(ks * 32);
            uint32_t ah[2][4], al[2][4], bb[4][4];
            #pragma unroll
            for (int mt = 0; mt < 2; mt++) ldm_x4(ah[mt], aH + ko + mt * (16 * RSTRIDE));
            #pragma unroll
            for (int gq = 0; gq < 4; gq++)  ldm_x4(bb[gq], bH + ko + gq * (16 * RSTRIDE));
            #pragma unroll
            for (int mt = 0; mt < 2; mt++)
                #pragma unroll
                for (int gq = 0; gq < 4; gq++) {
                    mma_f16(c[mt][2 * gq],     ah[mt], bb[gq][0], bb[gq][1]);
                    mma_f16(c[mt][2 * gq + 1], ah[mt], bb[gq][2], bb[gq][3]);
                }
            #pragma unroll
            for (int mt = 0; mt < 2; mt++) ldm_x4(al[mt], aL + ko + mt * (16 * RSTRIDE));
            #pragma unroll
            for (int mt = 0; mt < 2; mt++)
                #pragma unroll
                for (int gq = 0; gq < 4; gq++) {
                    mma_f16(c[mt][2 * gq],     al[mt], bb[gq][0], bb[gq][1]);
                    mma_f16(c[mt][2 * gq + 1], al[mt], bb[gq][2], bb[gq][3]);
                }
        }

        if ((g & 63) == 63) {
            // epilogue for n-chunk nc = g>>6: tanh + v-dot, then reset accum
            const int n0 = (g >> 6) * 128;
            #pragma unroll
            for (int mt = 0; mt < 2; mt++) {
                #pragma unroll
                for (int nt = 0; nt < 8; nt++) {
                    const int h = n0 + wn * 64 + nt * 8 + 2 * (lane & 3);
                    float ca0 = cs[h], ca1 = cs[h + 1];
                    float v0 = vs[h], v1 = vs[h + 1];
                    float x0 = ca0 + c[mt][nt][0];
                    float x1 = ca1 + c[mt][nt][1];
                    float x2 = ca0 + c[mt][nt][2];
                    float x3 = ca1 + c[mt][nt][3];
                    float t0, t1, t2, t3;
                    asm("tanh.approx.f32 %0, %1;" : "=f"(t0) : "f"(x0));
                    asm("tanh.approx.f32 %0, %1;" : "=f"(t1) : "f"(x1));
                    asm("tanh.approx.f32 %0, %1;" : "=f"(t2) : "f"(x2));
                    asm("tanh.approx.f32 %0, %1;" : "=f"(t3) : "f"(x3));
                    esum[mt * 2 + 0] = fmaf(v0, t0, fmaf(v1, t1, esum[mt * 2 + 0]));
                    esum[mt * 2 + 1] = fmaf(v0, t2, fmaf(v1, t3, esum[mt * 2 + 1]));
                    c[mt][nt][0] = 0.f; c[mt][nt][1] = 0.f;
                    c[mt][nt][2] = 0.f; c[mt][nt][3] = 0.f;
                }
            }
        }
    }

    // ---- final row reduction ----
    #pragma unroll
    for (int i = 0; i < 4; i++) {
        esum[i] += __shfl_xor_sync(0xffffffffu, esum[i], 1);
        esum[i] += __shfl_xor_sync(0xffffffffu, esum[i], 2);
    }
    float* red = (float*)(smem + OFF_RED);
    __syncthreads();
    if (t < 128) red[t] = 0.f;
    __syncthreads();
    if ((lane & 3) == 0) {
        #pragma unroll
        for (int i = 0; i < 4; i++) {
            int row = wm * 32 + (i >> 1) * 16 + (lane >> 2) + (i & 1) * 8;
            atomicAdd(&red[row], esum[i]);
        }
    }
    __syncthreads();
    if (t < 128) g_energy[b * SRC + s0 + t] = red[t];
}

// ------------------------------------------------------------------
// K3: masked softmax over S per batch
// ------------------------------------------------------------------
__global__ void k3_softmax(const void* __restrict__ mask_raw, float* __restrict__ out) {
    const int b = blockIdx.x, t = threadIdx.x;
    const int lane = t & 31, wid = t >> 5;
    __shared__ int s_mode;
    __shared__ float sm[16];
    __shared__ float s_bcast;
    if (t == 0) s_mode = 0;
    __syncthreads();
    if (t < 256) {
        unsigned w = ((const unsigned*)mask_raw)[t];
        if (w > 1u) atomicOr(&s_mode, 1);
    }
    __syncthreads();
    int masked = s_mode ? (int)((const unsigned char*)mask_raw)[b * SRC + t]
                        : ((const int*)mask_raw)[b * SRC + t];
    float e = masked ? NEGV : g_energy[b * SRC + t];

    float m = e;
    #pragma unroll
    for (int off = 16; off; off >>= 1) m = fmaxf(m, __shfl_xor_sync(0xffffffffu, m, off));
    if (lane == 0) sm[wid] = m;
    __syncthreads();
    if (wid == 0) {
        float v = (lane < 16) ? sm[lane] : -3.4e38f;
        #pragma unroll
        for (int off = 8; off; off >>= 1) v = fmaxf(v, __shfl_xor_sync(0xffffffffu, v, off));
        if (lane == 0) s_bcast = v;
    }
    __syncthreads();
    float p = __expf(e - s_bcast);
    float s = p;
    #pragma unroll
    for (int off = 16; off; off >>= 1) s += __shfl_xor_sync(0xffffffffu, s, off);
    __syncthreads();
    if (lane == 0) sm[wid] = s;
    __syncthreads();
    if (wid == 0) {
        float v = (lane < 16) ? sm[lane] : 0.f;
        #pragma unroll
        for (int off = 8; off; off >>= 1) v += __shfl_xor_sync(0xffffffffu, v, off);
        if (lane == 0) s_bcast = v;
    }
    __syncthreads();
    out[b * SRC + t] = p * __frcp_rn(s_bcast);
}

// ------------------------------------------------------------------
extern "C" void kernel_launch(void* const* d_in, const int* in_sizes, int n_in,
                              void* d_out, int out_size) {
    const float* hidden = (const float*)d_in[0];
    const float* enc    = (const float*)d_in[1];
    const void*  mask   = d_in[2];
    const float* W_w    = (const float*)d_in[3];
    const float* W_b    = (const float*)d_in[4];
    const float* U_w    = (const float*)d_in[5];
    const float* U_b    = (const float*)d_in[6];
    const float* v_w    = (const float*)d_in[7];
    float* out = (float*)d_out;

    static int attr_done = 0;
    if (!attr_done) {
        cudaFuncSetAttribute(k2_energy, cudaFuncAttributeMaxDynamicSharedMemorySize, SMEM_TOTAL);
        attr_done = 1;
    }

    conv_enc<<<65536, 256>>>(enc);
    conv_U<<<2048, 256>>>(U_w);
    k1_wh<<<dim3(8, 64), 256>>>(hidden, W_w, W_b, U_b);
    k2_energy<<<dim3(4, 64), 256, SMEM_TOTAL>>>(v_w);
    k3_softmax<<<BATCH, 512>>>(mask, out);
}

// round 5
// speedup vs baseline: 10.4141x; 2.1771x over previous
#include <cuda_runtime.h>
#include <cuda_fp16.h>
#include <cstdint>

#define BATCH 64
#define SRC   512
#define HID   1024
#define HID2  2048
#define NEGV  -1e10f
#define ARS   (BATCH * HID2)

// ------------------------------------------------------------------
// scratch (static device globals; no cudaMalloc allowed)
// ------------------------------------------------------------------
__device__ __align__(16) __half g_encH[SRC * BATCH * HID2];
__device__ __align__(16) __half g_UH[HID * HID2];
__device__ float g_c[BATCH * HID];
__device__ float g_energy[BATCH * SRC];

// ------------------------------------------------------------------
static __device__ __forceinline__ uint32_t smem_u32(const void* p) {
    uint32_t a;
    asm("{ .reg .u64 t; cvta.to.shared.u64 t, %1; cvt.u32.u64 %0, t; }" : "=r"(a) : "l"(p));
    return a;
}
static __device__ __forceinline__ void cp16(uint32_t dst, const void* src) {
    asm volatile("cp.async.cg.shared.global [%0], [%1], 16;" :: "r"(dst), "l"(src));
}
#define CP_COMMIT() asm volatile("cp.async.commit_group;" ::: "memory")
#define CP_WAIT(n)  asm volatile("cp.async.wait_group %0;" :: "n"(n) : "memory")

static __device__ __forceinline__ void ldm_x4(uint32_t* r, uint32_t addr) {
    asm volatile("ldmatrix.sync.aligned.m8n8.x4.shared.b16 {%0,%1,%2,%3}, [%4];"
                 : "=r"(r[0]), "=r"(r[1]), "=r"(r[2]), "=r"(r[3]) : "r"(addr));
}
static __device__ __forceinline__ void mma_f16(float* c, const uint32_t* a,
                                               uint32_t b0, uint32_t b1) {
    asm volatile(
        "mma.sync.aligned.m16n8k16.row.col.f32.f16.f16.f32 "
        "{%0,%1,%2,%3}, {%4,%5,%6,%7}, {%8,%9}, {%0,%1,%2,%3};"
        : "+f"(c[0]), "+f"(c[1]), "+f"(c[2]), "+f"(c[3])
        : "r"(a[0]), "r"(a[1]), "r"(a[2]), "r"(a[3]), "r"(b0), "r"(b1));
}

#define SWZ(o) ((uint32_t)(o) ^ ((((uint32_t)(o)) >> 3) & 0x70))

// SMEM layout: stage = A(128x64 fp16, 128B rows, SW128) + B(128x64)
#define STAGE_BYTES 32768
#define OFF_SB      16384                // B offset within stage
#define OFF_CS      98304                // after 3 stages
#define OFF_VS      102400
#define OFF_RED     106496
#define SMEM_TOTAL  107008

// ------------------------------------------------------------------
// prep: fp32 -> fp16
// ------------------------------------------------------------------
__global__ void conv_enc(const float* __restrict__ enc) {
    size_t i = (size_t)blockIdx.x * 256 + threadIdx.x;
    float4 v = ((const float4*)enc)[i];
    __half h[4] = {__float2half_rn(v.x), __float2half_rn(v.y),
                   __float2half_rn(v.z), __float2half_rn(v.w)};
    *(uint2*)(g_encH + 4 * i) = *(uint2*)h;
}
__global__ void conv_U(const float* __restrict__ U_w) {
    size_t i = (size_t)blockIdx.x * 256 + threadIdx.x;
    float4 v = ((const float4*)U_w)[i];
    __half h[4] = {__float2half_rn(v.x), __float2half_rn(v.y),
                   __float2half_rn(v.z), __float2half_rn(v.w)};
    *(uint2*)(g_UH + 4 * i) = *(uint2*)h;
}

// ------------------------------------------------------------------
// K1: g_c[b,h] = hidden[b,:] . W_w[h,:] + W_b[h] + U_b[h]
// ------------------------------------------------------------------
__global__ void k1_wh(const float* __restrict__ hidden,
                      const float* __restrict__ W_w,
                      const float* __restrict__ W_b,
                      const float* __restrict__ U_b) {
    int b = blockIdx.y, h0 = blockIdx.x * 128;
    __shared__ __align__(16) float hs[HID];
    int t = threadIdx.x;                    // 256
    ((float4*)hs)[t] = ((const float4*)(hidden + (size_t)b * HID))[t];
    __syncthreads();
    int w = t >> 5, lane = t & 31;
    #pragma unroll 4
    for (int hh = 0; hh < 16; hh++) {
        int h = h0 + w * 16 + hh;
        const float4* wr = (const float4*)(W_w + (size_t)h * HID);
        const float4* hr = (const float4*)hs;
        float s0 = 0.f, s1 = 0.f, s2 = 0.f, s3 = 0.f;
        #pragma unroll
        for (int i = 0; i < 8; i++) {
            float4 wv = wr[lane + i * 32];
            float4 hv = hr[lane + i * 32];
            s0 += wv.x * hv.x; s1 += wv.y * hv.y;
            s2 += wv.z * hv.z; s3 += wv.w * hv.w;
        }
        float s = (s0 + s1) + (s2 + s3);
        #pragma unroll
        for (int off = 16; off; off >>= 1) s += __shfl_xor_sync(0xffffffffu, s, off);
        if (lane == 0) g_c[b * HID + h] = s + W_b[h] + U_b[h];
    }
}

// ------------------------------------------------------------------
// K2: fp16 1-term mma.sync fused energy
//   energy[b,s] = sum_h v[h] * tanh(c[b,h] + sum_k enc[s,b,k]*U[h,k])
// CTA 256 thr, M=128 x N=128 per chunk (8 chunks), K-stage 64,
// 3-stage cp.async ring, 1 barrier per stage, SW128 rows.
// ------------------------------------------------------------------
static __device__ __forceinline__ void do_stage(uint32_t sb, int gg, int t,
                                                const __half* __restrict__ encHb) {
    const int nc = gg >> 5, kt = gg & 31;
    const int k0 = kt * 64, n0 = nc * 128;
    const uint32_t sbase = sb + ((uint32_t)gg % 3u) * STAGE_BYTES;
    #pragma unroll
    for (int i = 0; i < 4; i++) {
        int idx = t + i * 256;                 // 0..1023
        int r = idx >> 3, kb = idx & 7;
        uint32_t so = SWZ(r * 128 + kb * 16);
        cp16(sbase + so, encHb + (size_t)r * ARS + k0 + kb * 8);
        cp16(sbase + OFF_SB + so, g_UH + (size_t)(n0 + r) * HID2 + k0 + kb * 8);
    }
}

__global__ __launch_bounds__(256, 2) void k2_energy(const float* __restrict__ v_w) {
    extern __shared__ __align__(128) char smem[];
    const uint32_t sb = smem_u32(smem);
    const int b = blockIdx.y, s0 = blockIdx.x * 128;
    const int t = threadIdx.x, wid = t >> 5, lane = t & 31;
    const int wm = wid & 3, wn = wid >> 2;

    float* cs = (float*)(smem + OFF_CS);
    float* vs = (float*)(smem + OFF_VS);
    for (int i = t; i < HID; i += 256) { cs[i] = g_c[b * HID + i]; vs[i] = v_w[i]; }

    const __half* encHb = g_encH + ((size_t)s0 * BATCH + b) * HID2;

    // per-thread pre-swizzle byte offsets (swizzle applied per use with ks)
    uint32_t aBase[2], bBase[4];
    #pragma unroll
    for (int mt = 0; mt < 2; mt++)
        aBase[mt] = (uint32_t)((wm * 32 + mt * 16 + (lane & 15)) * 128 + (lane >> 4) * 16);
    #pragma unroll
    for (int gq = 0; gq < 4; gq++)
        bBase[gq] = (uint32_t)((wn * 64 + gq * 16 + (lane & 7) + ((lane >> 4) << 3)) * 128
                               + ((lane >> 3) & 1) * 16);

    float c[2][8][4];
    #pragma unroll
    for (int mt = 0; mt < 2; mt++)
        #pragma unroll
        for (int nt = 0; nt < 8; nt++)
            #pragma unroll
            for (int e = 0; e < 4; e++) c[mt][nt][e] = 0.f;
    float esum[4] = {0.f, 0.f, 0.f, 0.f};

    do_stage(sb, 0, t, encHb);
    CP_COMMIT();
    do_stage(sb, 1, t, encHb);
    CP_COMMIT();

    for (int g = 0; g < 256; g++) {
        CP_WAIT(1);
        __syncthreads();
        if (g < 254) do_stage(sb, g + 2, t, encHb);
        CP_COMMIT();

        const uint32_t sbase = sb + ((uint32_t)g % 3u) * STAGE_BYTES;

        #pragma unroll
        for (int ks = 0; ks < 4; ks++) {
            const uint32_t ko = (uint32_t)(ks * 32);
            uint32_t ah[2][4], bb[4][4];
            #pragma unroll
            for (int mt = 0; mt < 2; mt++) ldm_x4(ah[mt], sbase + SWZ(aBase[mt] + ko));
            #pragma unroll
            for (int gq = 0; gq < 4; gq++)
                ldm_x4(bb[gq], sbase + OFF_SB + SWZ(bBase[gq] + ko));
            #pragma unroll
            for (int mt = 0; mt < 2; mt++)
                #pragma unroll
                for (int gq = 0; gq < 4; gq++) {
                    mma_f16(c[mt][2 * gq],     ah[mt], bb[gq][0], bb[gq][1]);
                    mma_f16(c[mt][2 * gq + 1], ah[mt], bb[gq][2], bb[gq][3]);
                }
        }

        if ((g & 31) == 31) {
            // epilogue for n-chunk nc = g>>5: tanh + v-dot, then reset accum
            const int n0 = (g >> 5) * 128;
            #pragma unroll
            for (int mt = 0; mt < 2; mt++) {
                #pragma unroll
                for (int nt = 0; nt < 8; nt++) {
                    const int h = n0 + wn * 64 + nt * 8 + 2 * (lane & 3);
                    float ca0 = cs[h], ca1 = cs[h + 1];
                    float v0 = vs[h], v1 = vs[h + 1];
                    float x0 = ca0 + c[mt][nt][0];
                    float x1 = ca1 + c[mt][nt][1];
                    float x2 = ca0 + c[mt][nt][2];
                    float x3 = ca1 + c[mt][nt][3];
                    float t0, t1, t2, t3;
                    asm("tanh.approx.f32 %0, %1;" : "=f"(t0) : "f"(x0));
                    asm("tanh.approx.f32 %0, %1;" : "=f"(t1) : "f"(x1));
                    asm("tanh.approx.f32 %0, %1;" : "=f"(t2) : "f"(x2));
                    asm("tanh.approx.f32 %0, %1;" : "=f"(t3) : "f"(x3));
                    esum[mt * 2 + 0] = fmaf(v0, t0, fmaf(v1, t1, esum[mt * 2 + 0]));
                    esum[mt * 2 + 1] = fmaf(v0, t2, fmaf(v1, t3, esum[mt * 2 + 1]));
                    c[mt][nt][0] = 0.f; c[mt][nt][1] = 0.f;
                    c[mt][nt][2] = 0.f; c[mt][nt][3] = 0.f;
                }
            }
        }
    }

    // ---- final row reduction ----
    #pragma unroll
    for (int i = 0; i < 4; i++) {
        esum[i] += __shfl_xor_sync(0xffffffffu, esum[i], 1);
        esum[i] += __shfl_xor_sync(0xffffffffu, esum[i], 2);
    }
    float* red = (float*)(smem + OFF_RED);
    __syncthreads();
    if (t < 128) red[t] = 0.f;
    __syncthreads();
    if ((lane & 3) == 0) {
        #pragma unroll
        for (int i = 0; i < 4; i++) {
            int row = wm * 32 + (i >> 1) * 16 + (lane >> 2) + (i & 1) * 8;
            atomicAdd(&red[row], esum[i]);
        }
    }
    __syncthreads();
    if (t < 128) g_energy[b * SRC + s0 + t] = red[t];
}

// ------------------------------------------------------------------
// K3: masked softmax over S per batch
// ------------------------------------------------------------------
__global__ void k3_softmax(const void* __restrict__ mask_raw, float* __restrict__ out) {
    const int b = blockIdx.x, t = threadIdx.x;
    const int lane = t & 31, wid = t >> 5;
    __shared__ int s_mode;
    __shared__ float sm[16];
    __shared__ float s_bcast;
    if (t == 0) s_mode = 0;
    __syncthreads();
    if (t < 256) {
        unsigned w = ((const unsigned*)mask_raw)[t];
        if (w > 1u) atomicOr(&s_mode, 1);
    }
    __syncthreads();
    int masked = s_mode ? (int)((const unsigned char*)mask_raw)[b * SRC + t]
                        : ((const int*)mask_raw)[b * SRC + t];
    float e = masked ? NEGV : g_energy[b * SRC + t];

    float m = e;
    #pragma unroll
    for (int off = 16; off; off >>= 1) m = fmaxf(m, __shfl_xor_sync(0xffffffffu, m, off));
    if (lane == 0) sm[wid] = m;
    __syncthreads();
    if (wid == 0) {
        float v = (lane < 16) ? sm[lane] : -3.4e38f;
        #pragma unroll
        for (int off = 8; off; off >>= 1) v = fmaxf(v, __shfl_xor_sync(0xffffffffu, v, off));
        if (lane == 0) s_bcast = v;
    }
    __syncthreads();
    float p = __expf(e - s_bcast);
    float s = p;
    #pragma unroll
    for (int off = 16; off; off >>= 1) s += __shfl_xor_sync(0xffffffffu, s, off);
    __syncthreads();
    if (lane == 0) sm[wid] = s;
    __syncthreads();
    if (wid == 0) {
        float v = (lane < 16) ? sm[lane] : 0.f;
        #pragma unroll
        for (int off = 8; off; off >>= 1) v += __shfl_xor_sync(0xffffffffu, v, off);
        if (lane == 0) s_bcast = v;
    }
    __syncthreads();
    out[b * SRC + t] = p * __frcp_rn(s_bcast);
}

// ------------------------------------------------------------------
extern "C" void kernel_launch(void* const* d_in, const int* in_sizes, int n_in,
                              void* d_out, int out_size) {
    const float* hidden = (const float*)d_in[0];
    const float* enc    = (const float*)d_in[1];
    const void*  mask   = d_in[2];
    const float* W_w    = (const float*)d_in[3];
    const float* W_b    = (const float*)d_in[4];
    const float* U_w    = (const float*)d_in[5];
    const float* U_b    = (const float*)d_in[6];
    const float* v_w    = (const float*)d_in[7];
    float* out = (float*)d_out;

    static int attr_done = 0;
    if (!attr_done) {
        cudaFuncSetAttribute(k2_energy, cudaFuncAttributeMaxDynamicSharedMemorySize, SMEM_TOTAL);
        attr_done = 1;
    }

    conv_enc<<<65536, 256>>>(enc);
    conv_U<<<2048, 256>>>(U_w);
    k1_wh<<<dim3(8, 64), 256>>>(hidden, W_w, W_b, U_b);
    k2_energy<<<dim3(4, 64), 256, SMEM_TOTAL>>>(v_w);
    k3_softmax<<<BATCH, 512>>>(mask, out);
}

// round 6
// speedup vs baseline: 11.9043x; 1.1431x over previous
#include <cuda_runtime.h>
#include <cuda_fp16.h>
#include <cstdint>

#define BATCH 64
#define SRC   512
#define HID   1024
#define HID2  2048
#define NEGV  -1e10f
#define ARS   (BATCH * HID2)

// ------------------------------------------------------------------
// scratch (static device globals; no cudaMalloc allowed)
// ------------------------------------------------------------------
__device__ __align__(16) __half g_encH[SRC * BATCH * HID2];
__device__ __align__(16) __half g_UH[HID * HID2];
__device__ float g_c[BATCH * HID];
__device__ float g_part[8 * BATCH * SRC];   // per-nc partial energies

// ------------------------------------------------------------------
static __device__ __forceinline__ uint32_t smem_u32(const void* p) {
    uint32_t a;
    asm("{ .reg .u64 t; cvta.to.shared.u64 t, %1; cvt.u32.u64 %0, t; }" : "=r"(a) : "l"(p));
    return a;
}
static __device__ __forceinline__ void cp16(uint32_t dst, const void* src) {
    asm volatile("cp.async.cg.shared.global [%0], [%1], 16;" :: "r"(dst), "l"(src));
}
#define CP_COMMIT() asm volatile("cp.async.commit_group;" ::: "memory")
#define CP_WAIT(n)  asm volatile("cp.async.wait_group %0;" :: "n"(n) : "memory")

static __device__ __forceinline__ void ldm_x4(uint32_t* r, uint32_t addr) {
    asm volatile("ldmatrix.sync.aligned.m8n8.x4.shared.b16 {%0,%1,%2,%3}, [%4];"
                 : "=r"(r[0]), "=r"(r[1]), "=r"(r[2]), "=r"(r[3]) : "r"(addr));
}
static __device__ __forceinline__ void mma_f16(float* c, const uint32_t* a,
                                               uint32_t b0, uint32_t b1) {
    asm volatile(
        "mma.sync.aligned.m16n8k16.row.col.f32.f16.f16.f32 "
        "{%0,%1,%2,%3}, {%4,%5,%6,%7}, {%8,%9}, {%0,%1,%2,%3};"
        : "+f"(c[0]), "+f"(c[1]), "+f"(c[2]), "+f"(c[3])
        : "r"(a[0]), "r"(a[1]), "r"(a[2]), "r"(a[3]), "r"(b0), "r"(b1));
}

#define SWZ(o) ((uint32_t)(o) ^ ((((uint32_t)(o)) >> 3) & 0x70))

// SMEM layout: stage = A(128x64 fp16, 128B rows, SW128) + B(128x64)
#define STAGE_BYTES 32768
#define OFF_SB      16384                // B offset within stage
#define OFF_CS      98304                // 128 floats (this nc's c values)
#define OFF_VS      98816                // 128 floats
#define OFF_RED     99328                // 256 floats
#define SMEM_TOTAL  100352

// ------------------------------------------------------------------
// prep: fp32 -> fp16
// ------------------------------------------------------------------
__global__ void conv_enc(const float* __restrict__ enc) {
    size_t i = (size_t)blockIdx.x * 256 + threadIdx.x;
    float4 v = ((const float4*)enc)[i];
    __half h[4] = {__float2half_rn(v.x), __float2half_rn(v.y),
                   __float2half_rn(v.z), __float2half_rn(v.w)};
    *(uint2*)(g_encH + 4 * i) = *(uint2*)h;
}
__global__ void conv_U(const float* __restrict__ U_w) {
    size_t i = (size_t)blockIdx.x * 256 + threadIdx.x;
    float4 v = ((const float4*)U_w)[i];
    __half h[4] = {__float2half_rn(v.x), __float2half_rn(v.y),
                   __float2half_rn(v.z), __float2half_rn(v.w)};
    *(uint2*)(g_UH + 4 * i) = *(uint2*)h;
}

// ------------------------------------------------------------------
// K1: g_c[b,h] = hidden[b,:] . W_w[h,:] + W_b[h] + U_b[h]
// ------------------------------------------------------------------
__global__ void k1_wh(const float* __restrict__ hidden,
                      const float* __restrict__ W_w,
                      const float* __restrict__ W_b,
                      const float* __restrict__ U_b) {
    int b = blockIdx.y, h0 = blockIdx.x * 128;
    __shared__ __align__(16) float hs[HID];
    int t = threadIdx.x;                    // 256
    ((float4*)hs)[t] = ((const float4*)(hidden + (size_t)b * HID))[t];
    __syncthreads();
    int w = t >> 5, lane = t & 31;
    #pragma unroll 4
    for (int hh = 0; hh < 16; hh++) {
        int h = h0 + w * 16 + hh;
        const float4* wr = (const float4*)(W_w + (size_t)h * HID);
        const float4* hr = (const float4*)hs;
        float s0 = 0.f, s1 = 0.f, s2 = 0.f, s3 = 0.f;
        #pragma unroll
        for (int i = 0; i < 8; i++) {
            float4 wv = wr[lane + i * 32];
            float4 hv = hr[lane + i * 32];
            s0 += wv.x * hv.x; s1 += wv.y * hv.y;
            s2 += wv.z * hv.z; s3 += wv.w * hv.w;
        }
        float s = (s0 + s1) + (s2 + s3);
        #pragma unroll
        for (int off = 16; off; off >>= 1) s += __shfl_xor_sync(0xffffffffu, s, off);
        if (lane == 0) g_c[b * HID + h] = s + W_b[h] + U_b[h];
    }
}

// ------------------------------------------------------------------
// K2: fp16 mma.sync fused energy, one (s-tile, nc, b) work item per CTA.
//   part[nc][b,s] = sum_{h in nc} v[h] * tanh(c[b,h] + sum_k enc[s,b,k]*U[h,k])
// grid (32, 64): blockIdx.x = st | (nc<<2). CTA 256 thr, M=128 x N=128,
// K = 2048 in 32 stages of 64, 3-stage cp.async ring, SW128 rows.
// ------------------------------------------------------------------
static __device__ __forceinline__ void do_stage(uint32_t sb, int kt, int t, int n0,
                                                const __half* __restrict__ encHb) {
    const int k0 = kt * 64;
    const uint32_t sbase = sb + ((uint32_t)kt % 3u) * STAGE_BYTES;
    #pragma unroll
    for (int i = 0; i < 4; i++) {
        int idx = t + i * 256;                 // 0..1023
        int r = idx >> 3, kb = idx & 7;
        uint32_t so = SWZ(r * 128 + kb * 16);
        cp16(sbase + so, encHb + (size_t)r * ARS + k0 + kb * 8);
        cp16(sbase + OFF_SB + so, g_UH + (size_t)(n0 + r) * HID2 + k0 + kb * 8);
    }
}

__global__ __launch_bounds__(256, 2) void k2_energy(const float* __restrict__ v_w) {
    extern __shared__ __align__(128) char smem[];
    const uint32_t sb = smem_u32(smem);
    const int b = blockIdx.y;
    const int st = blockIdx.x & 3, nc = blockIdx.x >> 2;
    const int s0 = st * 128, n0 = nc * 128;
    const int t = threadIdx.x, wid = t >> 5, lane = t & 31;
    const int wm = wid & 3, wn = wid >> 2;

    float* cs = (float*)(smem + OFF_CS);      // 128 entries (this nc)
    float* vs = (float*)(smem + OFF_VS);
    if (t < 128) { cs[t] = g_c[b * HID + n0 + t]; vs[t] = v_w[n0 + t]; }

    const __half* encHb = g_encH + ((size_t)s0 * BATCH + b) * HID2;

    uint32_t aBase[2], bBase[4];
    #pragma unroll
    for (int mt = 0; mt < 2; mt++)
        aBase[mt] = (uint32_t)((wm * 32 + mt * 16 + (lane & 15)) * 128 + (lane >> 4) * 16);
    #pragma unroll
    for (int gq = 0; gq < 4; gq++)
        bBase[gq] = (uint32_t)((wn * 64 + gq * 16 + (lane & 7) + ((lane >> 4) << 3)) * 128
                               + ((lane >> 3) & 1) * 16);

    float c[2][8][4];
    #pragma unroll
    for (int mt = 0; mt < 2; mt++)
        #pragma unroll
        for (int nt = 0; nt < 8; nt++)
            #pragma unroll
            for (int e = 0; e < 4; e++) c[mt][nt][e] = 0.f;

    do_stage(sb, 0, t, n0, encHb);
    CP_COMMIT();
    do_stage(sb, 1, t, n0, encHb);
    CP_COMMIT();

    for (int g = 0; g < 32; g++) {
        CP_WAIT(1);
        __syncthreads();
        if (g < 30) do_stage(sb, g + 2, t, n0, encHb);
        CP_COMMIT();

        const uint32_t sbase = sb + ((uint32_t)g % 3u) * STAGE_BYTES;

        #pragma unroll
        for (int ks = 0; ks < 4; ks++) {
            const uint32_t ko = (uint32_t)(ks * 32);
            uint32_t ah[2][4], bb[4][4];
            #pragma unroll
            for (int mt = 0; mt < 2; mt++) ldm_x4(ah[mt], sbase + SWZ(aBase[mt] + ko));
            #pragma unroll
            for (int gq = 0; gq < 4; gq++)
                ldm_x4(bb[gq], sbase + OFF_SB + SWZ(bBase[gq] + ko));
            #pragma unroll
            for (int mt = 0; mt < 2; mt++)
                #pragma unroll
                for (int gq = 0; gq < 4; gq++) {
                    mma_f16(c[mt][2 * gq],     ah[mt], bb[gq][0], bb[gq][1]);
                    mma_f16(c[mt][2 * gq + 1], ah[mt], bb[gq][2], bb[gq][3]);
                }
        }
        __syncthreads();
    }

    // ---- epilogue: tanh + v-dot over this CTA's 128 h columns ----
    float esum[4] = {0.f, 0.f, 0.f, 0.f};
    #pragma unroll
    for (int mt = 0; mt < 2; mt++) {
        #pragma unroll
        for (int nt = 0; nt < 8; nt++) {
            const int hl = wn * 64 + nt * 8 + 2 * (lane & 3);   // local h
            float ca0 = cs[hl], ca1 = cs[hl + 1];
            float v0 = vs[hl], v1 = vs[hl + 1];
            float x0 = ca0 + c[mt][nt][0];
            float x1 = ca1 + c[mt][nt][1];
            float x2 = ca0 + c[mt][nt][2];
            float x3 = ca1 + c[mt][nt][3];
            float t0, t1, t2, t3;
            asm("tanh.approx.f32 %0, %1;" : "=f"(t0) : "f"(x0));
            asm("tanh.approx.f32 %0, %1;" : "=f"(t1) : "f"(x1));
            asm("tanh.approx.f32 %0, %1;" : "=f"(t2) : "f"(x2));
            asm("tanh.approx.f32 %0, %1;" : "=f"(t3) : "f"(x3));
            esum[mt * 2 + 0] = fmaf(v0, t0, fmaf(v1, t1, esum[mt * 2 + 0]));
            esum[mt * 2 + 1] = fmaf(v0, t2, fmaf(v1, t3, esum[mt * 2 + 1]));
        }
    }

    // ---- deterministic row reduction (no atomics) ----
    #pragma unroll
    for (int i = 0; i < 4; i++) {
        esum[i] += __shfl_xor_sync(0xffffffffu, esum[i], 1);
        esum[i] += __shfl_xor_sync(0xffffffffu, esum[i], 2);
    }
    float* red = (float*)(smem + OFF_RED);    // [2][128] by wn
    if ((lane & 3) == 0) {
        #pragma unroll
        for (int i = 0; i < 4; i++) {
            int row = wm * 32 + (i >> 1) * 16 + (lane >> 2) + (i & 1) * 8;
            red[wn * 128 + row] = esum[i];
        }
    }
    __syncthreads();
    if (t < 128)
        g_part[(size_t)nc * (BATCH * SRC) + b * SRC + s0 + t] = red[t] + red[128 + t];
}

// ------------------------------------------------------------------
// K3: masked softmax over S per batch (sums the 8 nc partials)
// ------------------------------------------------------------------
__global__ void k3_softmax(const void* __restrict__ mask_raw, float* __restrict__ out) {
    const int b = blockIdx.x, t = threadIdx.x;
    const int lane = t & 31, wid = t >> 5;
    __shared__ int s_mode;
    __shared__ float sm[16];
    __shared__ float s_bcast;
    if (t == 0) s_mode = 0;
    __syncthreads();
    if (t < 256) {
        unsigned w = ((const unsigned*)mask_raw)[t];
        if (w > 1u) atomicOr(&s_mode, 1);
    }
    __syncthreads();
    int masked = s_mode ? (int)((const unsigned char*)mask_raw)[b * SRC + t]
                        : ((const int*)mask_raw)[b * SRC + t];
    float e;
    if (masked) {
        e = NEGV;
    } else {
        e = 0.f;
        #pragma unroll
        for (int nc = 0; nc < 8; nc++)
            e += g_part[(size_t)nc * (BATCH * SRC) + b * SRC + t];
    }

    float m = e;
    #pragma unroll
    for (int off = 16; off; off >>= 1) m = fmaxf(m, __shfl_xor_sync(0xffffffffu, m, off));
    if (lane == 0) sm[wid] = m;
    __syncthreads();
    if (wid == 0) {
        float v = (lane < 16) ? sm[lane] : -3.4e38f;
        #pragma unroll
        for (int off = 8; off; off >>= 1) v = fmaxf(v, __shfl_xor_sync(0xffffffffu, v, off));
        if (lane == 0) s_bcast = v;
    }
    __syncthreads();
    float p = __expf(e - s_bcast);
    float s = p;
    #pragma unroll
    for (int off = 16; off; off >>= 1) s += __shfl_xor_sync(0xffffffffu, s, off);
    __syncthreads();
    if (lane == 0) sm[wid] = s;
    __syncthreads();
    if (wid == 0) {
        float v = (lane < 16) ? sm[lane] : 0.f;
        #pragma unroll
        for (int off = 8; off; off >>= 1) v += __shfl_xor_sync(0xffffffffu, v, off);
        if (lane == 0) s_bcast = v;
    }
    __syncthreads();
    out[b * SRC + t] = p * __frcp_rn(s_bcast);
}

// ------------------------------------------------------------------
extern "C" void kernel_launch(void* const* d_in, const int* in_sizes, int n_in,
                              void* d_out, int out_size) {
    const float* hidden = (const float*)d_in[0];
    const float* enc    = (const float*)d_in[1];
    const void*  mask   = d_in[2];
    const float* W_w    = (const float*)d_in[3];
    const float* W_b    = (const float*)d_in[4];
    const float* U_w    = (const float*)d_in[5];
    const float* U_b    = (const float*)d_in[6];
    const float* v_w    = (const float*)d_in[7];
    float* out = (float*)d_out;

    static int attr_done = 0;
    if (!attr_done) {
        cudaFuncSetAttribute(k2_energy, cudaFuncAttributeMaxDynamicSharedMemorySize, SMEM_TOTAL);
        attr_done = 1;
    }

    conv_enc<<<65536, 256>>>(enc);
    conv_U<<<2048, 256>>>(U_w);
    k1_wh<<<dim3(8, 64), 256>>>(hidden, W_w, W_b, U_b);
    k2_energy<<<dim3(32, 64), 256, SMEM_TOTAL>>>(v_w);
    k3_softmax<<<BATCH, 512>>>(mask, out);
}